// round 9
// baseline (speedup 1.0000x reference)
#include <cuda_runtime.h>

// Problem constants
#define NB     2
#define NL     8192
#define NHID   1024
#define NSTATE 16
#define USTR   3072            // u channel stride = 3*HID
#define CHUNK  64
#define NCHUNK (NL / CHUNK)    // 128
#define CHB    128             // channels per block

// Per-chunk carry scratch: [chunk][b*HID + c][32]  (0..15 = fwd, 16..31 = bwd)
__device__ float g_carr[(size_t)NCHUNK * NB * NHID * 32];
// Materialized x1v: [b][t][c]
__device__ float g_xv[(size_t)NB * NL * NHID];

// ---- packed fp32x2 helpers (sm_103a FFMA2 path, PTX-only) ----
typedef unsigned long long u64;

__device__ __forceinline__ u64 pk2(float lo, float hi) {
    u64 r; asm("mov.b64 %0,{%1,%2};" : "=l"(r) : "f"(lo), "f"(hi)); return r;
}
__device__ __forceinline__ float2 up2(u64 v) {
    float2 r; asm("mov.b64 {%0,%1},%2;" : "=f"(r.x), "=f"(r.y) : "l"(v)); return r;
}
__device__ __forceinline__ u64 fma2_(u64 a, u64 b, u64 c) {
    u64 d; asm("fma.rn.f32x2 %0,%1,%2,%3;" : "=l"(d) : "l"(a), "l"(b), "l"(c)); return d;
}
__device__ __forceinline__ u64 mul2_(u64 a, u64 b) {
    u64 d; asm("mul.rn.f32x2 %0,%1,%2;" : "=l"(d) : "l"(a), "l"(b)); return d;
}
__device__ __forceinline__ u64 add2_(u64 a, u64 b) {
    u64 d; asm("add.rn.f32x2 %0,%1,%2;" : "=l"(d) : "l"(a), "l"(b)); return d;
}

__device__ __forceinline__ void pf_l1(const float* p) {
    asm volatile("prefetch.global.L1 [%0];" :: "l"(p));
}

__device__ __forceinline__ float ldu(const float* __restrict__ ub, int t, int uc) {
    return (t >= 0 && t < NL) ? ub[(size_t)t * USTR + uc] : 0.0f;
}
__device__ __forceinline__ int clampt(int t) {
    return t < 0 ? 0 : (t > NL - 1 ? NL - 1 : t);
}

// ---------------------------------------------------------------------------
// K1 (256 thr): stage 1 — split-half x1v FIR -> smem tile + g_xv; 8-batch
//               loads with L1 prefetch of the next batch (no register
//               double-buffer). stage 2 — half 0: ascending Sf; half 1:
//               descending Sb (Horner). float4 carry stores.
// ---------------------------------------------------------------------------
__global__ void __launch_bounds__(256)
k1_sums(const float* __restrict__ u, const float* __restrict__ w,
        const float* __restrict__ logp)
{
    __shared__ float xs[CHUNK * CHB];    // 32 KB, [t_local][c_local]

    const int j  = blockIdx.x;
    const int b  = blockIdx.z;
    const int lc = threadIdx.x & 127;
    const int half = threadIdx.x >> 7;
    const int c  = blockIdx.y * CHB + lc;
    const int hh = c >> 6, d = c & 63;
    const int uc1 = hh * 192 + 64 + d;
    const int ucv = hh * 192 + 128 + d;
    const float* ub = u + (size_t)b * NL * USTR;
    float* xvp = g_xv + ((size_t)b * NL) * NHID + c;

    const float w1a = w[uc1 * 3 + 0], w1b = w[uc1 * 3 + 1], w1c = 2.0f * w[uc1 * 3 + 2];
    const float wva = w[ucv * 3 + 0], wvb = w[ucv * 3 + 1], wvc = 2.0f * w[ucv * 3 + 2];

    const int t0 = j * CHUNK;
    const int ts = t0 + half * 32;       // this half's 32-step FIR span

    // ---- stage 1: FIR over [ts, ts+32), L1-prefetched batches ----
    {
        float a0 = ldu(ub, ts - 2, uc1), a1 = ldu(ub, ts - 1, uc1), a2 = ldu(ub, ts, uc1),
              a3 = ldu(ub, ts + 1, uc1), a4 = ldu(ub, ts + 2, uc1);
        float e0 = ldu(ub, ts - 2, ucv), e1 = ldu(ub, ts - 1, ucv), e2 = ldu(ub, ts, ucv),
              e3 = ldu(ub, ts + 1, ucv), e4 = ldu(ub, ts + 2, ucv);

        for (int base = 0; base < 32; base += 8) {
            // prefetch next batch's lines (no regs held)
            if (base < 24) {
#pragma unroll
                for (int k = 0; k < 8; k++) {
                    int tp = clampt(ts + base + k + 11);
                    pf_l1(ub + (size_t)tp * USTR + uc1);
                    pf_l1(ub + (size_t)tp * USTR + ucv);
                }
            }
            float an[8], en[8];
#pragma unroll
            for (int k = 0; k < 8; k++) {
                an[k] = ldu(ub, ts + base + k + 3, uc1);
                en[k] = ldu(ub, ts + base + k + 3, ucv);
            }
#pragma unroll
            for (int k = 0; k < 8; k++) {
                float z1 = fmaf(w1a, a0 + a4, fmaf(w1b, a1 + a3, w1c * a2));
                float zv = fmaf(wva, e0 + e4, fmaf(wvb, e1 + e3, wvc * e2));
                float x  = z1 * zv;
                xs[(half * 32 + base + k) * CHB + lc] = x;
                xvp[(size_t)(ts + base + k) * NHID] = x;
                a0 = a1; a1 = a2; a2 = a3; a3 = a4; a4 = an[k];
                e0 = e1; e1 = e2; e2 = e3; e3 = e4; e4 = en[k];
            }
        }
    }
    __syncthreads();

    // ---- stage 2: one-direction scan over the full 64-step tile ----
    u64 p2[8], S[8];
#pragma unroll
    for (int m = 0; m < 8; m++) {
        p2[m] = pk2(expf(logp[2 * m]), expf(logp[2 * m + 1]));
        S[m] = 0ULL;
    }

    float4* dst4 = (float4*)(g_carr +
        ((size_t)j * (NB * NHID) + (size_t)b * NHID + c) * 32 + half * 16);

    if (half == 0) {
        // ascending: Sf = sum_i p^(63-i) x[i]
        for (int base = 0; base < CHUNK; base += 8) {
            float v[8];
#pragma unroll
            for (int k = 0; k < 8; k++) v[k] = xs[(base + k) * CHB + lc];
#pragma unroll
            for (int k = 0; k < 8; k++) {
                u64 xx = pk2(v[k], v[k]);
#pragma unroll
                for (int m = 0; m < 8; m++) S[m] = fma2_(p2[m], S[m], xx);
            }
        }
    } else {
        // descending: Sb = sum_i p^i x[i]  (Horner, no powers)
        for (int base = CHUNK - 8; base >= 0; base -= 8) {
            float v[8];
#pragma unroll
            for (int k = 0; k < 8; k++) v[k] = xs[(base + k) * CHB + lc];
#pragma unroll
            for (int k = 7; k >= 0; k--) {
                u64 xx = pk2(v[k], v[k]);
#pragma unroll
                for (int m = 0; m < 8; m++) S[m] = fma2_(p2[m], S[m], xx);
            }
        }
    }
    // float4 carry stores (both halves)
#pragma unroll
    for (int m = 0; m < 4; m++) {
        float2 lo = up2(S[2 * m]), hi = up2(S[2 * m + 1]);
        dst4[m] = make_float4(lo.x, lo.y, hi.x, hi.y);
    }
}

// ---------------------------------------------------------------------------
// K2: in-place affine exclusive scan across chunks per (b,c,mode,dir),
//     8-deep batched loads.  (unchanged)
// ---------------------------------------------------------------------------
__global__ void k2_scan(const float* __restrict__ logp)
{
    const int tid = blockIdx.x * blockDim.x + threadIdx.x;
    if (tid >= NB * NHID * 32) return;
    const int dirm = tid & 31;
    const int bc   = tid >> 5;
    const int m    = dirm & 15;
    const int dir  = dirm >> 4;
    const float q  = expf(logp[m] * (float)CHUNK);

    const size_t stride = (size_t)(NB * NHID) * 32;
    float* base = g_carr + (size_t)bc * 32 + dirm;
    float carry = 0.0f;
    if (dir == 0) {
        for (int jb = 0; jb < NCHUNK; jb += 8) {
            float s[8];
#pragma unroll
            for (int k = 0; k < 8; k++) s[k] = base[(size_t)(jb + k) * stride];
#pragma unroll
            for (int k = 0; k < 8; k++) {
                base[(size_t)(jb + k) * stride] = carry;
                carry = fmaf(q, carry, s[k]);
            }
        }
    } else {
        for (int jb = NCHUNK - 8; jb >= 0; jb -= 8) {
            float s[8];
#pragma unroll
            for (int k = 0; k < 8; k++) s[k] = base[(size_t)(jb + k) * stride];
#pragma unroll
            for (int k = 7; k >= 0; k--) {
                base[(size_t)(jb + k) * stride] = carry;
                carry = fmaf(q, carry, s[k]);
            }
        }
    }
}

// ---------------------------------------------------------------------------
// K3: fused two-sweep over g_xv, 2 chunks per block. L1 prefetch: next xv
//     batch in both sweeps, plus sweep-2's x2 gate lines during sweep 1.
//     float4 carry loads. ysm columns thread-private (no syncs).
// ---------------------------------------------------------------------------
__global__ void __launch_bounds__(CHB)
k3_apply(const float* __restrict__ u, const float* __restrict__ w,
         const float* __restrict__ logp, const float* __restrict__ resid,
         const float* __restrict__ Dp, float* __restrict__ out)
{
    __shared__ float ysm[CHUNK * CHB];   // 32 KB

    const int c = blockIdx.y * CHB + threadIdx.x;
    const int b = blockIdx.z;
    const int hh = c >> 6, d = c & 63;
    const int uc2 = hh * 192 + d;        // x2 (gate)
    const float* ub  = u + (size_t)b * NL * USTR;
    const float* xvp = g_xv + ((size_t)b * NL) * NHID + c;

    const float w2a = w[uc2 * 3 + 0], w2b = w[uc2 * 3 + 1], w2c = 2.0f * w[uc2 * 3 + 2];

    u64 p2[8], r2[8];
#pragma unroll
    for (int m = 0; m < 8; m++) {
        p2[m] = pk2(expf(logp[2 * m]), expf(logp[2 * m + 1]));
        r2[m] = pk2(resid[2 * m], resid[2 * m + 1]);
    }
    const float Dc = Dp[c];

    for (int cc = 0; cc < 2; cc++) {
        const int j = blockIdx.x * 2 + cc;
        const int t0 = j * CHUNK;

        // float4 carry loads: 32 floats = 8 float4
        const float4* cp4 = (const float4*)(g_carr +
            ((size_t)j * (NB * NHID) + (size_t)b * NHID + c) * 32);
        float4 cf[4], cb[4];
#pragma unroll
        for (int m = 0; m < 4; m++) { cf[m] = cp4[m]; cb[m] = cp4[4 + m]; }

        // ---- sweep 1: descending (backward recurrence) ----
        {
            u64 Bk[8];
#pragma unroll
            for (int m = 0; m < 4; m++) {
                Bk[2 * m]     = pk2(cb[m].x, cb[m].y);
                Bk[2 * m + 1] = pk2(cb[m].z, cb[m].w);
            }

            for (int base = CHUNK - 8; base >= 0; base -= 8) {
                // prefetch next xv batch + this batch's x2 gate lines
#pragma unroll
                for (int k = 0; k < 8; k++) {
                    if (base >= 8)
                        pf_l1(xvp + (size_t)(t0 + base - 8 + k) * NHID);
                    pf_l1(ub + (size_t)clampt(t0 + base + k) * USTR + uc2);
                }
                float vx[8];
#pragma unroll
                for (int k = 0; k < 8; k++) vx[k] = xvp[(size_t)(t0 + base + k) * NHID];
#pragma unroll
                for (int k = 7; k >= 0; k--) {
                    float x = vx[k];
                    u64 xx = pk2(x, x);
#pragma unroll
                    for (int m = 0; m < 8; m++) Bk[m] = fma2_(p2[m], Bk[m], xx);
                    u64 ac0 = mul2_(r2[0], Bk[0]), ac1 = mul2_(r2[1], Bk[1]);
#pragma unroll
                    for (int m = 2; m < 8; m += 2) {
                        ac0 = fma2_(r2[m], Bk[m], ac0);
                        ac1 = fma2_(r2[m + 1], Bk[m + 1], ac1);
                    }
                    float2 s = up2(add2_(ac0, ac1));
                    ysm[(base + k) * CHB + threadIdx.x] = fmaf(Dc, x, s.x + s.y);
                }
            }
        }

        // ---- sweep 2: ascending (forward recurrence + output gate) ----
        u64 F[8];
#pragma unroll
        for (int m = 0; m < 4; m++) {
            F[2 * m]     = pk2(cf[m].x, cf[m].y);
            F[2 * m + 1] = pk2(cf[m].z, cf[m].w);
        }

        float g0 = ldu(ub, t0 - 2, uc2), g1 = ldu(ub, t0 - 1, uc2), g2 = ldu(ub, t0, uc2),
              g3 = ldu(ub, t0 + 1, uc2), g4 = ldu(ub, t0 + 2, uc2);
        float* op = out + ((size_t)b * NL + t0) * NHID + c;

        for (int base = 0; base < CHUNK; base += 8) {
            if (base < CHUNK - 8) {
#pragma unroll
                for (int k = 0; k < 8; k++)
                    pf_l1(xvp + (size_t)(t0 + base + 8 + k) * NHID);
            }
            float vx[8], gs[8];
#pragma unroll
            for (int k = 0; k < 8; k++) {
                vx[k] = xvp[(size_t)(t0 + base + k) * NHID];
                gs[k] = ldu(ub, t0 + base + k + 3, uc2);
            }
#pragma unroll
            for (int k = 0; k < 8; k++) {
                u64 xx = pk2(vx[k], vx[k]);
#pragma unroll
                for (int m = 0; m < 8; m++) F[m] = fma2_(p2[m], F[m], xx);
                u64 ac0 = mul2_(r2[0], F[0]), ac1 = mul2_(r2[1], F[1]);
#pragma unroll
                for (int m = 2; m < 8; m += 2) {
                    ac0 = fma2_(r2[m], F[m], ac0);
                    ac1 = fma2_(r2[m + 1], F[m + 1], ac1);
                }
                float2 s = up2(add2_(ac0, ac1));
                float z2 = fmaf(w2a, g0 + g4, fmaf(w2b, g1 + g3, w2c * g2));
                float y  = s.x + s.y + ysm[(base + k) * CHB + threadIdx.x];
                op[(size_t)(base + k) * NHID] = y * z2;
                g0 = g1; g1 = g2; g2 = g3; g3 = g4; g4 = gs[k];
            }
        }
    }
}

// ---------------------------------------------------------------------------
extern "C" void kernel_launch(void* const* d_in, const int* in_sizes, int n_in,
                              void* d_out, int out_size)
{
    const float* u     = (const float*)d_in[0];
    const float* w     = (const float*)d_in[1];
    const float* logp  = (const float*)d_in[2];
    const float* resid = (const float*)d_in[3];
    const float* Dp    = (const float*)d_in[4];
    float* out = (float*)d_out;

    dim3 grid1(NCHUNK, NHID / CHB, NB);      // (128, 8, 2)
    k1_sums<<<grid1, 256>>>(u, w, logp);

    const int nscan = NB * NHID * 32;        // 65536
    k2_scan<<<(nscan + 255) / 256, 256>>>(logp);

    dim3 grid3(NCHUNK / 2, NHID / CHB, NB);  // (64, 8, 2)
    k3_apply<<<grid3, CHB>>>(u, w, logp, resid, Dp, out);
}

// round 10
// speedup vs baseline: 1.4768x; 1.4768x over previous
#include <cuda_runtime.h>

// Problem constants
#define NB     2
#define NL     8192
#define NHID   1024
#define NSTATE 16
#define USTR   3072            // u channel stride = 3*HID
#define CHUNK  64
#define NCHUNK (NL / CHUNK)    // 128
#define CHB    128             // channels per block

// Per-chunk carry scratch: [chunk][b*HID + c][32]  (0..15 = fwd, 16..31 = bwd)
__device__ float g_carr[(size_t)NCHUNK * NB * NHID * 32];
// Materialized x1v: [b][t][c]
__device__ float g_xv[(size_t)NB * NL * NHID];

// ---- packed fp32x2 helpers (sm_103a FFMA2 path, PTX-only) ----
typedef unsigned long long u64;

__device__ __forceinline__ u64 pk2(float lo, float hi) {
    u64 r; asm("mov.b64 %0,{%1,%2};" : "=l"(r) : "f"(lo), "f"(hi)); return r;
}
__device__ __forceinline__ float2 up2(u64 v) {
    float2 r; asm("mov.b64 {%0,%1},%2;" : "=f"(r.x), "=f"(r.y) : "l"(v)); return r;
}
__device__ __forceinline__ u64 fma2_(u64 a, u64 b, u64 c) {
    u64 d; asm("fma.rn.f32x2 %0,%1,%2,%3;" : "=l"(d) : "l"(a), "l"(b), "l"(c)); return d;
}
__device__ __forceinline__ u64 mul2_(u64 a, u64 b) {
    u64 d; asm("mul.rn.f32x2 %0,%1,%2;" : "=l"(d) : "l"(a), "l"(b)); return d;
}
__device__ __forceinline__ u64 add2_(u64 a, u64 b) {
    u64 d; asm("add.rn.f32x2 %0,%1,%2;" : "=l"(d) : "l"(a), "l"(b)); return d;
}

__device__ __forceinline__ float ldu(const float* __restrict__ ub, int t, int uc) {
    return (t >= 0 && t < NL) ? ub[(size_t)t * USTR + uc] : 0.0f;
}

// ---------------------------------------------------------------------------
// K1 (256 thr): stage 1 — split-half x1v FIR -> smem tile + g_xv (simple
//               8-deep batches, no pipelining). stage 2 — half 0: ascending
//               Sf; half 1: descending Sb (Horner). float4 carry stores.
// ---------------------------------------------------------------------------
__global__ void __launch_bounds__(256)
k1_sums(const float* __restrict__ u, const float* __restrict__ w,
        const float* __restrict__ logp)
{
    __shared__ float xs[CHUNK * CHB];    // 32 KB, [t_local][c_local]

    const int j  = blockIdx.x;
    const int b  = blockIdx.z;
    const int lc = threadIdx.x & 127;
    const int half = threadIdx.x >> 7;
    const int c  = blockIdx.y * CHB + lc;
    const int hh = c >> 6, d = c & 63;
    const int uc1 = hh * 192 + 64 + d;
    const int ucv = hh * 192 + 128 + d;
    const float* ub = u + (size_t)b * NL * USTR;
    float* xvp = g_xv + ((size_t)b * NL) * NHID + c;

    const float w1a = w[uc1 * 3 + 0], w1b = w[uc1 * 3 + 1], w1c = 2.0f * w[uc1 * 3 + 2];
    const float wva = w[ucv * 3 + 0], wvb = w[ucv * 3 + 1], wvc = 2.0f * w[ucv * 3 + 2];

    const int t0 = j * CHUNK;
    const int ts = t0 + half * 32;       // this half's 32-step FIR span

    // ---- stage 1: FIR over [ts, ts+32) ----
    {
        float a0 = ldu(ub, ts - 2, uc1), a1 = ldu(ub, ts - 1, uc1), a2 = ldu(ub, ts, uc1),
              a3 = ldu(ub, ts + 1, uc1), a4 = ldu(ub, ts + 2, uc1);
        float e0 = ldu(ub, ts - 2, ucv), e1 = ldu(ub, ts - 1, ucv), e2 = ldu(ub, ts, ucv),
              e3 = ldu(ub, ts + 1, ucv), e4 = ldu(ub, ts + 2, ucv);

        for (int base = 0; base < 32; base += 8) {
            float an[8], en[8];
#pragma unroll
            for (int k = 0; k < 8; k++) {
                an[k] = ldu(ub, ts + base + k + 3, uc1);
                en[k] = ldu(ub, ts + base + k + 3, ucv);
            }
#pragma unroll
            for (int k = 0; k < 8; k++) {
                float z1 = fmaf(w1a, a0 + a4, fmaf(w1b, a1 + a3, w1c * a2));
                float zv = fmaf(wva, e0 + e4, fmaf(wvb, e1 + e3, wvc * e2));
                float x  = z1 * zv;
                xs[(half * 32 + base + k) * CHB + lc] = x;
                xvp[(size_t)(ts + base + k) * NHID] = x;
                a0 = a1; a1 = a2; a2 = a3; a3 = a4; a4 = an[k];
                e0 = e1; e1 = e2; e2 = e3; e3 = e4; e4 = en[k];
            }
        }
    }
    __syncthreads();

    // ---- stage 2: one-direction scan over the full 64-step tile ----
    u64 p2[8], S[8];
#pragma unroll
    for (int m = 0; m < 8; m++) {
        p2[m] = pk2(expf(logp[2 * m]), expf(logp[2 * m + 1]));
        S[m] = 0ULL;
    }

    if (half == 0) {
        // ascending: Sf = sum_i p^(63-i) x[i]
        for (int base = 0; base < CHUNK; base += 8) {
            float v[8];
#pragma unroll
            for (int k = 0; k < 8; k++) v[k] = xs[(base + k) * CHB + lc];
#pragma unroll
            for (int k = 0; k < 8; k++) {
                u64 xx = pk2(v[k], v[k]);
#pragma unroll
                for (int m = 0; m < 8; m++) S[m] = fma2_(p2[m], S[m], xx);
            }
        }
    } else {
        // descending: Sb = sum_i p^i x[i]  (Horner, no powers)
        for (int base = CHUNK - 8; base >= 0; base -= 8) {
            float v[8];
#pragma unroll
            for (int k = 0; k < 8; k++) v[k] = xs[(base + k) * CHB + lc];
#pragma unroll
            for (int k = 7; k >= 0; k--) {
                u64 xx = pk2(v[k], v[k]);
#pragma unroll
                for (int m = 0; m < 8; m++) S[m] = fma2_(p2[m], S[m], xx);
            }
        }
    }

    // float4 carry stores: fwd at +0 (half 0), bwd at +16 (half 1)
    float4* dst4 = (float4*)(g_carr +
        ((size_t)j * (NB * NHID) + (size_t)b * NHID + c) * 32 + half * 16);
#pragma unroll
    for (int m = 0; m < 4; m++) {
        float2 lo = up2(S[2 * m]), hi = up2(S[2 * m + 1]);
        dst4[m] = make_float4(lo.x, lo.y, hi.x, hi.y);
    }
}

// ---------------------------------------------------------------------------
// K2: in-place affine exclusive scan across chunks per (b,c,mode,dir),
//     8-deep batched loads.  (unchanged)
// ---------------------------------------------------------------------------
__global__ void k2_scan(const float* __restrict__ logp)
{
    const int tid = blockIdx.x * blockDim.x + threadIdx.x;
    if (tid >= NB * NHID * 32) return;
    const int dirm = tid & 31;
    const int bc   = tid >> 5;
    const int m    = dirm & 15;
    const int dir  = dirm >> 4;
    const float q  = expf(logp[m] * (float)CHUNK);

    const size_t stride = (size_t)(NB * NHID) * 32;
    float* base = g_carr + (size_t)bc * 32 + dirm;
    float carry = 0.0f;
    if (dir == 0) {
        for (int jb = 0; jb < NCHUNK; jb += 8) {
            float s[8];
#pragma unroll
            for (int k = 0; k < 8; k++) s[k] = base[(size_t)(jb + k) * stride];
#pragma unroll
            for (int k = 0; k < 8; k++) {
                base[(size_t)(jb + k) * stride] = carry;
                carry = fmaf(q, carry, s[k]);
            }
        }
    } else {
        for (int jb = NCHUNK - 8; jb >= 0; jb -= 8) {
            float s[8];
#pragma unroll
            for (int k = 0; k < 8; k++) s[k] = base[(size_t)(jb + k) * stride];
#pragma unroll
            for (int k = 7; k >= 0; k--) {
                base[(size_t)(jb + k) * stride] = carry;
                carry = fmaf(q, carry, s[k]);
            }
        }
    }
}

// ---------------------------------------------------------------------------
// K3: fused two-sweep over g_xv, 2 chunks per block, float4 carry loads,
//     simple 8-deep batches (no prefetch, no double-buffer). ysm columns
//     are thread-private: no syncthreads needed.
// ---------------------------------------------------------------------------
__global__ void __launch_bounds__(CHB)
k3_apply(const float* __restrict__ u, const float* __restrict__ w,
         const float* __restrict__ logp, const float* __restrict__ resid,
         const float* __restrict__ Dp, float* __restrict__ out)
{
    __shared__ float ysm[CHUNK * CHB];   // 32 KB

    const int c = blockIdx.y * CHB + threadIdx.x;
    const int b = blockIdx.z;
    const int hh = c >> 6, d = c & 63;
    const int uc2 = hh * 192 + d;        // x2 (gate)
    const float* ub  = u + (size_t)b * NL * USTR;
    const float* xvp = g_xv + ((size_t)b * NL) * NHID + c;

    const float w2a = w[uc2 * 3 + 0], w2b = w[uc2 * 3 + 1], w2c = 2.0f * w[uc2 * 3 + 2];

    u64 p2[8], r2[8];
#pragma unroll
    for (int m = 0; m < 8; m++) {
        p2[m] = pk2(expf(logp[2 * m]), expf(logp[2 * m + 1]));
        r2[m] = pk2(resid[2 * m], resid[2 * m + 1]);
    }
    const float Dc = Dp[c];

#pragma unroll 1
    for (int cc = 0; cc < 2; cc++) {
        const int j = blockIdx.x * 2 + cc;
        const int t0 = j * CHUNK;

        // float4 carry loads: 32 floats = 8 float4 (fwd 0..3, bwd 4..7)
        const float4* cp4 = (const float4*)(g_carr +
            ((size_t)j * (NB * NHID) + (size_t)b * NHID + c) * 32);
        float4 cf[4], cb[4];
#pragma unroll
        for (int m = 0; m < 4; m++) { cf[m] = cp4[m]; cb[m] = cp4[4 + m]; }

        // ---- sweep 1: descending (backward recurrence) ----
        {
            u64 Bk[8];
#pragma unroll
            for (int m = 0; m < 4; m++) {
                Bk[2 * m]     = pk2(cb[m].x, cb[m].y);
                Bk[2 * m + 1] = pk2(cb[m].z, cb[m].w);
            }

            for (int base = CHUNK - 8; base >= 0; base -= 8) {
                float vx[8];
#pragma unroll
                for (int k = 0; k < 8; k++) vx[k] = xvp[(size_t)(t0 + base + k) * NHID];
#pragma unroll
                for (int k = 7; k >= 0; k--) {
                    float x = vx[k];
                    u64 xx = pk2(x, x);
#pragma unroll
                    for (int m = 0; m < 8; m++) Bk[m] = fma2_(p2[m], Bk[m], xx);
                    u64 ac0 = mul2_(r2[0], Bk[0]), ac1 = mul2_(r2[1], Bk[1]);
#pragma unroll
                    for (int m = 2; m < 8; m += 2) {
                        ac0 = fma2_(r2[m], Bk[m], ac0);
                        ac1 = fma2_(r2[m + 1], Bk[m + 1], ac1);
                    }
                    float2 s = up2(add2_(ac0, ac1));
                    ysm[(base + k) * CHB + threadIdx.x] = fmaf(Dc, x, s.x + s.y);
                }
            }
        }

        // ---- sweep 2: ascending (forward recurrence + output gate) ----
        u64 F[8];
#pragma unroll
        for (int m = 0; m < 4; m++) {
            F[2 * m]     = pk2(cf[m].x, cf[m].y);
            F[2 * m + 1] = pk2(cf[m].z, cf[m].w);
        }

        float g0 = ldu(ub, t0 - 2, uc2), g1 = ldu(ub, t0 - 1, uc2), g2 = ldu(ub, t0, uc2),
              g3 = ldu(ub, t0 + 1, uc2), g4 = ldu(ub, t0 + 2, uc2);
        float* op = out + ((size_t)b * NL + t0) * NHID + c;

        for (int base = 0; base < CHUNK; base += 8) {
            float vx[8], gs[8];
#pragma unroll
            for (int k = 0; k < 8; k++) {
                vx[k] = xvp[(size_t)(t0 + base + k) * NHID];
                gs[k] = ldu(ub, t0 + base + k + 3, uc2);
            }
#pragma unroll
            for (int k = 0; k < 8; k++) {
                u64 xx = pk2(vx[k], vx[k]);
#pragma unroll
                for (int m = 0; m < 8; m++) F[m] = fma2_(p2[m], F[m], xx);
                u64 ac0 = mul2_(r2[0], F[0]), ac1 = mul2_(r2[1], F[1]);
#pragma unroll
                for (int m = 2; m < 8; m += 2) {
                    ac0 = fma2_(r2[m], F[m], ac0);
                    ac1 = fma2_(r2[m + 1], F[m + 1], ac1);
                }
                float2 s = up2(add2_(ac0, ac1));
                float z2 = fmaf(w2a, g0 + g4, fmaf(w2b, g1 + g3, w2c * g2));
                float y  = s.x + s.y + ysm[(base + k) * CHB + threadIdx.x];
                op[(size_t)(base + k) * NHID] = y * z2;
                g0 = g1; g1 = g2; g2 = g3; g3 = g4; g4 = gs[k];
            }
        }
    }
}

// ---------------------------------------------------------------------------
extern "C" void kernel_launch(void* const* d_in, const int* in_sizes, int n_in,
                              void* d_out, int out_size)
{
    const float* u     = (const float*)d_in[0];
    const float* w     = (const float*)d_in[1];
    const float* logp  = (const float*)d_in[2];
    const float* resid = (const float*)d_in[3];
    const float* Dp    = (const float*)d_in[4];
    float* out = (float*)d_out;

    dim3 grid1(NCHUNK, NHID / CHB, NB);      // (128, 8, 2)
    k1_sums<<<grid1, 256>>>(u, w, logp);

    const int nscan = NB * NHID * 32;        // 65536
    k2_scan<<<(nscan + 255) / 256, 256>>>(logp);

    dim3 grid3(NCHUNK / 2, NHID / CHB, NB);  // (64, 8, 2)
    k3_apply<<<grid3, CHB>>>(u, w, logp, resid, Dp, out);
}